// round 12
// baseline (speedup 1.0000x reference)
#include <cuda_runtime.h>

#define Bb     8
#define Nn     3136
#define Cc     64
#define CI     32
#define BNROWS 25088          // Bb * Nn
#define LAMF   0.1f
#define HSTEP  0.05f
#define BNEPS  1e-3f
#define INVN   (1.0f / 3136.0f)

typedef unsigned long long u64;

// ---- scratch (static device globals; no allocation) ----
__device__ float d_theta[BNROWS * CI];
__device__ float d_phi[BNROWS * CI];
__device__ float d_phisum[Bb * CI];
__device__ float d_pspart[784 * CI];     // per-block phi-sum partials
__device__ float d_M[2][Bb * 2048];      // phi^T g per iter; zeroed in k_theta_phi
__device__ float d_g1[BNROWS * Cc];

__device__ __forceinline__ void redg_v4(float* p, float a, float b, float c, float d) {
    asm volatile("red.global.add.v4.f32 [%0], {%1, %2, %3, %4};"
                 :: "l"(p), "f"(a), "f"(b), "f"(c), "f"(d) : "memory");
}
// packed f32x2 helpers (Blackwell): 2 MACs per FMA-pipe issue
__device__ __forceinline__ u64 fdup(float x) {
    u64 r; asm("mov.b64 %0, {%1, %1};" : "=l"(r) : "f"(x)); return r;
}
__device__ __forceinline__ void ffma2(u64& d, u64 a, u64 b) {
    asm("fma.rn.f32x2 %0, %1, %2, %0;" : "+l"(d) : "l"(a), "l"(b));
}
__device__ __forceinline__ float2 unpk(u64 v) {
    float2 r; asm("mov.b64 {%0, %1}, %2;" : "=f"(r.x), "=f"(r.y) : "l"(v)); return r;
}
__device__ __forceinline__ void ldpair(const float* p, u64& b01, u64& b23) {
    double2 d = *(const double2*)p;
    b01 = __double_as_longlong(d.x);
    b23 = __double_as_longlong(d.y);
}

// ===========================================================================
// K1: theta/phi = x @ Wt/Wp + bias; per-block phi-sum partials; blocks 0-31
// zero both d_M buffers (this kernel never touches d_M otherwise).
__global__ void __launch_bounds__(256) k_theta_phi(
        const float* __restrict__ x,
        const float* __restrict__ Wt, const float* __restrict__ bt,
        const float* __restrict__ Wp, const float* __restrict__ bp) {
    __shared__ float sx[32 * 64];
    __shared__ float sWt[32 * 68];
    __shared__ float sWp[32 * 68];
    __shared__ float sp[32];
    int t  = threadIdx.x;
    int gb = blockIdx.x;
    int r0 = gb * 32;

    if (gb < 32) {   // zero both M buffers: 8192 float4 total
        float4 z = make_float4(0.f, 0.f, 0.f, 0.f);
        ((float4*)d_M)[gb * 256 + t] = z;
    }
    {
        const float4* src = (const float4*)(x + r0 * 64);
        ((float4*)sx)[t]       = src[t];
        ((float4*)sx)[t + 256] = src[t + 256];
    }
    for (int e = t; e < 2048; e += 256) {   // weights transposed
        int k = e >> 5, d = e & 31;
        sWt[d * 68 + k] = Wt[e];
        sWp[d * 68 + k] = Wp[e];
    }
    if (t < 32) sp[t] = 0.f;
    __syncthreads();

    int w = t >> 5, d = t & 31;
    float th[4], ph[4];
    float bt_d = bt[d], bp_d = bp[d];
#pragma unroll
    for (int j = 0; j < 4; j++) { th[j] = bt_d; ph[j] = bp_d; }

    const float* xr = sx + w * 4 * 64;
    const float* wt = sWt + d * 68;
    const float* wp = sWp + d * 68;
#pragma unroll
    for (int k = 0; k < 64; k += 4) {
        float4 a = *(const float4*)(wt + k);
        float4 b = *(const float4*)(wp + k);
#pragma unroll
        for (int j = 0; j < 4; j++) {
            float4 xv = *(const float4*)(xr + j * 64 + k);
            th[j] = fmaf(xv.x, a.x, th[j]); th[j] = fmaf(xv.y, a.y, th[j]);
            th[j] = fmaf(xv.z, a.z, th[j]); th[j] = fmaf(xv.w, a.w, th[j]);
            ph[j] = fmaf(xv.x, b.x, ph[j]); ph[j] = fmaf(xv.y, b.y, ph[j]);
            ph[j] = fmaf(xv.z, b.z, ph[j]); ph[j] = fmaf(xv.w, b.w, ph[j]);
        }
    }
    int r = r0 + w * 4;
    float phs = 0.f;
#pragma unroll
    for (int j = 0; j < 4; j++) {
        d_theta[(r + j) * 32 + d] = th[j];
        d_phi[(r + j) * 32 + d]   = ph[j];
        phs += ph[j];
    }
    atomicAdd(&sp[d], phs);
    __syncthreads();
    if (t < 32) d_pspart[gb * 32 + t] = sp[t];
}

// ===========================================================================
// K2/K4: M[iter][b] += phi[b]^T @ g[b]. 64 rows/block, grid 392.
// R9 structure; inner loop converted to packed FFMA2 (col pairs).
template<int ITER>
__global__ void __launch_bounds__(256) k_reduceM(const float* __restrict__ x) {
    const float* g = ITER ? d_g1 : x;
    __shared__ float sm[6144];              // 24 KB
    float* sph = sm;                        // [64][32]
    float* sg  = sm + 2048;                 // [64][64]

    int t     = threadIdx.x;
    int b     = blockIdx.x / 49;
    int chunk = blockIdx.x % 49;
    int row0  = b * Nn + chunk * 64;

    if (ITER == 0 && chunk == 0 && t < 32) {
        float a = 0.f;
        for (int j = 0; j < 98; j++) a += d_pspart[(b * 98 + j) * 32 + t];
        d_phisum[b * 32 + t] = a;
    }

    {
        const float4* phg = (const float4*)(d_phi + row0 * 32);
        const float4* gg  = (const float4*)(g + row0 * 64);
        ((float4*)sph)[t]       = phg[t];
        ((float4*)sph)[t + 256] = phg[t + 256];
        ((float4*)sg)[t]        = gg[t];
        ((float4*)sg)[t + 256]  = gg[t + 256];
        ((float4*)sg)[t + 512]  = gg[t + 512];
        ((float4*)sg)[t + 768]  = gg[t + 768];
    }
    __syncthreads();

    int rg = t >> 7;              // row group 0..1 (32 rows each)
    int u  = t & 127;
    int d0 = (u >> 4) * 4;        // 0,4,...,28
    int c0 = (u & 15) * 4;        // 0,4,...,60

    u64 acc2[4][2];
#pragma unroll
    for (int i = 0; i < 4; i++) { acc2[i][0] = 0ull; acc2[i][1] = 0ull; }

    const float* P = sph + rg * 32 * 32;
    const float* G = sg + rg * 32 * 64;
#pragma unroll 8
    for (int j = 0; j < 32; j++) {
        float4 p = *(const float4*)(P + j * 32 + d0);
        u64 g01, g23; ldpair(G + j * 64 + c0, g01, g23);
        u64 p0 = fdup(p.x), p1 = fdup(p.y), p2 = fdup(p.z), p3 = fdup(p.w);
        ffma2(acc2[0][0], p0, g01); ffma2(acc2[0][1], p0, g23);
        ffma2(acc2[1][0], p1, g01); ffma2(acc2[1][1], p1, g23);
        ffma2(acc2[2][0], p2, g01); ffma2(acc2[2][1], p2, g23);
        ffma2(acc2[3][0], p3, g01); ffma2(acc2[3][1], p3, g23);
    }
    __syncthreads();   // staged tiles fully consumed; overlay partials

    // write partials: part[rg][d][c], row stride 68
    float* part = sm;
#pragma unroll
    for (int di = 0; di < 4; di++) {
        float2 lo = unpk(acc2[di][0]), hi = unpk(acc2[di][1]);
        *(float4*)(part + rg * 2176 + (d0 + di) * 68 + c0) =
            make_float4(lo.x, lo.y, hi.x, hi.y);
    }
    __syncthreads();

    // reduce 2 groups + emit
    int dd = t >> 3, cc = (t & 7) * 8;
    const float* p0 = part + dd * 68 + cc;
    float4 a0 = *(const float4*)(p0);
    float4 a1 = *(const float4*)(p0 + 4);
    float4 b0 = *(const float4*)(p0 + 2176);
    float4 b1 = *(const float4*)(p0 + 2176 + 4);
    float* Mb = d_M[ITER] + b * 2048 + dd * 64 + cc;
    redg_v4(Mb,     a0.x + b0.x, a0.y + b0.y, a0.z + b0.z, a0.w + b0.w);
    redg_v4(Mb + 4, a1.x + b1.x, a1.y + b1.y, a1.z + b1.z, a1.w + b1.w);
}

// ===========================================================================
// K3/K5: two-phase apply; inner GEMMs converted to packed FFMA2.
//   phase1: raw = theta @ M (K=32); fg = (lam/N)*raw - (s/N)*g
//   phase2: o = fg @ W + bias; BN; ReLU; out = x + 0.05*o
template<int ITER>
__global__ void __launch_bounds__(256) k_apply(
        const float* __restrict__ x,
        const float* __restrict__ Wst, const float* __restrict__ bst,
        const float* __restrict__ gam, const float* __restrict__ bet,
        const float* __restrict__ mmean, const float* __restrict__ mvar,
        float* __restrict__ out_ext) {
    const float* gin = ITER ? d_g1 : x;
    float* out       = ITER ? out_ext : d_g1;

    __shared__ float sm[8800];
    float* sAt  = sm;          // theta^T [k=32][row 64] pad 68   (2176)
    float* sM   = sm + 2176;   // M [k=32][col 64] pad 68          (2176)
    float* sW   = sm + 4352;   // W [k=64][col 64] pad 68          (4352)
    float* sfgT = sm;          // fg^T [k=64][row 64] pad 68, overlays sAt+sM
    float* ss   = sm + 8704;   // 64
    float* sps  = sm + 8768;   // 32

    int t  = threadIdx.x;
    int r0 = blockIdx.x * 64;
    int b  = blockIdx.x / 49;

    // stage theta^T
#pragma unroll
    for (int j = 0; j < 2; j++) {
        int e = t + j * 256;
        int r = e >> 3, dd = (e & 7) * 4;
        float4 v = ((const float4*)(d_theta + r0 * 32))[e];
        sAt[(dd + 0) * 68 + r] = v.x;
        sAt[(dd + 1) * 68 + r] = v.y;
        sAt[(dd + 2) * 68 + r] = v.z;
        sAt[(dd + 3) * 68 + r] = v.w;
    }
    // stage M
    const float* Mi = d_M[ITER] + b * 2048;
#pragma unroll
    for (int j = 0; j < 2; j++) {
        int e = t + j * 256;
        int k = e >> 4, c4 = (e & 15) * 4;
        *(float4*)(sM + k * 68 + c4) = ((const float4*)Mi)[e];
    }
    // stage W
    const float* Wi = Wst + ITER * 4096;
#pragma unroll
    for (int j = 0; j < 4; j++) {
        int e = t + j * 256;
        int k = e >> 4, c4 = (e & 15) * 4;
        *(float4*)(sW + k * 68 + c4) = ((const float4*)Wi)[e];
    }
    if (t < 32) sps[t] = d_phisum[b * 32 + t];
    __syncthreads();

    if (t < 64) {   // -(s/N) per row, s = LAM * theta . phisum
        float a = 0.f;
#pragma unroll
        for (int k = 0; k < 32; k++) a = fmaf(sAt[k * 68 + t], sps[k], a);
        ss[t] = a * (-LAMF * INVN);
    }
    __syncthreads();

    int tx = t & 15, ty = t >> 4;
    int rr = ty * 4, cc = tx * 4;

    // ---- phase 1: raw = theta @ M (K=32), packed f32x2 over col pairs ----
    u64 fga[4][2];
#pragma unroll
    for (int i = 0; i < 4; i++) { fga[i][0] = 0ull; fga[i][1] = 0ull; }

#pragma unroll 8
    for (int k = 0; k < 32; k++) {
        float4 a = *(const float4*)(sAt + k * 68 + rr);
        u64 b01, b23; ldpair(sM + k * 68 + cc, b01, b23);
        u64 a0 = fdup(a.x), a1 = fdup(a.y), a2 = fdup(a.z), a3 = fdup(a.w);
        ffma2(fga[0][0], a0, b01); ffma2(fga[0][1], a0, b23);
        ffma2(fga[1][0], a1, b01); ffma2(fga[1][1], a1, b23);
        ffma2(fga[2][0], a2, b01); ffma2(fga[2][1], a2, b23);
        ffma2(fga[3][0], a3, b01); ffma2(fga[3][1], a3, b23);
    }
    float fg[4][4];
#pragma unroll
    for (int i = 0; i < 4; i++) {
        float2 lo = unpk(fga[i][0]), hi = unpk(fga[i][1]);
        fg[i][0] = lo.x; fg[i][1] = lo.y; fg[i][2] = hi.x; fg[i][3] = hi.y;
    }
    const float c1 = LAMF * INVN;
#pragma unroll
    for (int i = 0; i < 4; i++) {
        float sneg = ss[rr + i];
        float4 gv = *(const float4*)(gin + (r0 + rr + i) * 64 + cc);
        fg[i][0] = fmaf(sneg, gv.x, c1 * fg[i][0]);
        fg[i][1] = fmaf(sneg, gv.y, c1 * fg[i][1]);
        fg[i][2] = fmaf(sneg, gv.z, c1 * fg[i][2]);
        fg[i][3] = fmaf(sneg, gv.w, c1 * fg[i][3]);
    }
    __syncthreads();   // sAt/sM fully read; reuse as sfgT

    // store fg transposed: sfgT[k=col][row]
#pragma unroll
    for (int j = 0; j < 4; j++) {
        float4 v = make_float4(fg[0][j], fg[1][j], fg[2][j], fg[3][j]);
        *(float4*)(sfgT + (cc + j) * 68 + rr) = v;
    }
    __syncthreads();

    // ---- phase 2: o = fg @ W (K=64), packed f32x2 over col pairs ----
    u64 oac[4][2];
#pragma unroll
    for (int i = 0; i < 4; i++) { oac[i][0] = 0ull; oac[i][1] = 0ull; }

#pragma unroll 8
    for (int k = 0; k < 64; k++) {
        float4 a = *(const float4*)(sfgT + k * 68 + rr);
        u64 b01, b23; ldpair(sW + k * 68 + cc, b01, b23);
        u64 a0 = fdup(a.x), a1 = fdup(a.y), a2 = fdup(a.z), a3 = fdup(a.w);
        ffma2(oac[0][0], a0, b01); ffma2(oac[0][1], a0, b23);
        ffma2(oac[1][0], a1, b01); ffma2(oac[1][1], a1, b23);
        ffma2(oac[2][0], a2, b01); ffma2(oac[2][1], a2, b23);
        ffma2(oac[3][0], a3, b01); ffma2(oac[3][1], a3, b23);
    }
    float acc[4][4];
#pragma unroll
    for (int i = 0; i < 4; i++) {
        float2 lo = unpk(oac[i][0]), hi = unpk(oac[i][1]);
        acc[i][0] = lo.x; acc[i][1] = lo.y; acc[i][2] = hi.x; acc[i][3] = hi.y;
    }

    // epilogue: bias, BN, ReLU, residual (last == x always)
    float4 bias = *(const float4*)(bst + ITER * 64 + cc);
    float4 gm   = *(const float4*)(gam + ITER * 64 + cc);
    float4 bt4  = *(const float4*)(bet + ITER * 64 + cc);
    float4 mmv  = *(const float4*)(mmean + ITER * 64 + cc);
    float4 mv   = *(const float4*)(mvar + ITER * 64 + cc);
    float scl[4]  = { gm.x * rsqrtf(mv.x + BNEPS), gm.y * rsqrtf(mv.y + BNEPS),
                      gm.z * rsqrtf(mv.z + BNEPS), gm.w * rsqrtf(mv.w + BNEPS) };
    float bia[4]  = { bias.x, bias.y, bias.z, bias.w };
    float mean[4] = { mmv.x, mmv.y, mmv.z, mmv.w };
    float betc[4] = { bt4.x, bt4.y, bt4.z, bt4.w };

#pragma unroll
    for (int i = 0; i < 4; i++) {
        int r = r0 + rr + i;
        float4 xv = *(const float4*)(x + r * 64 + cc);
        float xa[4] = { xv.x, xv.y, xv.z, xv.w };
        float4 ov;
        float* op = (float*)&ov;
#pragma unroll
        for (int j = 0; j < 4; j++) {
            float o = acc[i][j] + bia[j];
            o = (o - mean[j]) * scl[j] + betc[j];
            o = fmaxf(o, 0.f);
            op[j] = xa[j] + HSTEP * o;
        }
        *(float4*)(out + r * 64 + cc) = ov;
    }
}

// ---------------------------------------------------------------------------
extern "C" void kernel_launch(void* const* d_in, const int* in_sizes, int n_in,
                              void* d_out, int out_size) {
    const float* x     = (const float*)d_in[0];
    const float* Wt    = (const float*)d_in[1];
    const float* bt    = (const float*)d_in[2];
    const float* Wp    = (const float*)d_in[3];
    const float* bp    = (const float*)d_in[4];
    const float* Wst   = (const float*)d_in[5];
    const float* bst   = (const float*)d_in[6];
    const float* gam   = (const float*)d_in[7];
    const float* bet   = (const float*)d_in[8];
    const float* mmean = (const float*)d_in[9];
    const float* mvar  = (const float*)d_in[10];
    float* out = (float*)d_out;

    k_theta_phi<<<BNROWS / 32, 256>>>(x, Wt, bt, Wp, bp);
    k_reduceM<0><<<Bb * 49, 256>>>(x);
    k_apply<0><<<BNROWS / 64, 256>>>(x, Wst, bst, gam, bet, mmean, mvar, out);
    k_reduceM<1><<<Bb * 49, 256>>>(x);
    k_apply<1><<<BNROWS / 64, 256>>>(x, Wst, bst, gam, bet, mmean, mvar, out);
}

// round 13
// speedup vs baseline: 1.7598x; 1.7598x over previous
#include <cuda_runtime.h>

#define Bb     8
#define Nn     3136
#define Cc     64
#define CI     32
#define BNROWS 25088          // Bb * Nn
#define LAMF   0.1f
#define HSTEP  0.05f
#define BNEPS  1e-3f
#define INVN   (1.0f / 3136.0f)

// ---- scratch (static device globals; no allocation) ----
__device__ float d_theta[BNROWS * CI];
__device__ float d_phi[BNROWS * CI];
__device__ float d_phisum[Bb * CI];
__device__ float d_pspart[784 * CI];     // per-block phi-sum partials
__device__ float d_M[2][Bb * 2048];      // phi^T g per iter; zeroed in k_theta_phi
__device__ float d_g1[BNROWS * Cc];

__device__ __forceinline__ void redg_v4(float* p, float a, float b, float c, float d) {
    asm volatile("red.global.add.v4.f32 [%0], {%1, %2, %3, %4};"
                 :: "l"(p), "f"(a), "f"(b), "f"(c), "f"(d) : "memory");
}
__device__ __forceinline__ unsigned tf32(float x) {
    unsigned r; asm("cvt.rna.tf32.f32 %0, %1;" : "=r"(r) : "f"(x)); return r;
}
// D += A(16x8,row) * B(8x8,col-ish n8), tf32 inputs, f32 accum
__device__ __forceinline__ void mma_tf32(float4& d,
        unsigned a0, unsigned a1, unsigned a2, unsigned a3,
        unsigned b0, unsigned b1) {
    asm("mma.sync.aligned.m16n8k8.row.col.f32.tf32.tf32.f32 "
        "{%0,%1,%2,%3}, {%4,%5,%6,%7}, {%8,%9}, {%0,%1,%2,%3};"
        : "+f"(d.x), "+f"(d.y), "+f"(d.z), "+f"(d.w)
        : "r"(a0), "r"(a1), "r"(a2), "r"(a3), "r"(b0), "r"(b1));
}

// ===========================================================================
// K1: theta/phi = x @ Wt/Wp + bias; per-block phi-sum partials; blocks 0-31
// zero both d_M buffers (this kernel never touches d_M otherwise). (R9 exact)
__global__ void __launch_bounds__(256) k_theta_phi(
        const float* __restrict__ x,
        const float* __restrict__ Wt, const float* __restrict__ bt,
        const float* __restrict__ Wp, const float* __restrict__ bp) {
    __shared__ float sx[32 * 64];
    __shared__ float sWt[32 * 68];
    __shared__ float sWp[32 * 68];
    __shared__ float sp[32];
    int t  = threadIdx.x;
    int gb = blockIdx.x;
    int r0 = gb * 32;

    if (gb < 32) {
        float4 z = make_float4(0.f, 0.f, 0.f, 0.f);
        ((float4*)d_M)[gb * 256 + t] = z;
    }
    {
        const float4* src = (const float4*)(x + r0 * 64);
        ((float4*)sx)[t]       = src[t];
        ((float4*)sx)[t + 256] = src[t + 256];
    }
    for (int e = t; e < 2048; e += 256) {
        int k = e >> 5, d = e & 31;
        sWt[d * 68 + k] = Wt[e];
        sWp[d * 68 + k] = Wp[e];
    }
    if (t < 32) sp[t] = 0.f;
    __syncthreads();

    int w = t >> 5, d = t & 31;
    float th[4], ph[4];
    float bt_d = bt[d], bp_d = bp[d];
#pragma unroll
    for (int j = 0; j < 4; j++) { th[j] = bt_d; ph[j] = bp_d; }

    const float* xr = sx + w * 4 * 64;
    const float* wt = sWt + d * 68;
    const float* wp = sWp + d * 68;
#pragma unroll
    for (int k = 0; k < 64; k += 4) {
        float4 a = *(const float4*)(wt + k);
        float4 b = *(const float4*)(wp + k);
#pragma unroll
        for (int j = 0; j < 4; j++) {
            float4 xv = *(const float4*)(xr + j * 64 + k);
            th[j] = fmaf(xv.x, a.x, th[j]); th[j] = fmaf(xv.y, a.y, th[j]);
            th[j] = fmaf(xv.z, a.z, th[j]); th[j] = fmaf(xv.w, a.w, th[j]);
            ph[j] = fmaf(xv.x, b.x, ph[j]); ph[j] = fmaf(xv.y, b.y, ph[j]);
            ph[j] = fmaf(xv.z, b.z, ph[j]); ph[j] = fmaf(xv.w, b.w, ph[j]);
        }
    }
    int r = r0 + w * 4;
    float phs = 0.f;
#pragma unroll
    for (int j = 0; j < 4; j++) {
        d_theta[(r + j) * 32 + d] = th[j];
        d_phi[(r + j) * 32 + d]   = ph[j];
        phs += ph[j];
    }
    atomicAdd(&sp[d], phs);
    __syncthreads();
    if (t < 32) d_pspart[gb * 32 + t] = sp[t];
}

// ===========================================================================
// K2/K4: M[iter][b] += phi[b]^T @ g[b] via tf32 MMA. 64 rows/block, grid 392.
// A = phi^T (m=d 32, k=row), B = g (k=row, n=c 64). 8 warps: warp w owns
// d-band (w&1)*16 and col tiles {(w>>1)*8, (w>>1)*8+32}. C frags -> smem
// partial -> R9-proven v4 REDG emission.
template<int ITER>
__global__ void __launch_bounds__(256) k_reduceM(const float* __restrict__ x) {
    const float* g = ITER ? d_g1 : x;
    __shared__ float sm[6656];
    float* sph  = sm;          // phi [row 64][d 32] pad 36  (2304)
    float* sg   = sm + 2304;   // g   [row 64][c 64] pad 68  (4352)
    float* part = sm;          // overlay: M partial [d 32][c 64] pad 68 (2176)

    int t     = threadIdx.x;
    int b     = blockIdx.x / 49;
    int chunk = blockIdx.x % 49;
    int row0  = b * Nn + chunk * 64;

    if (ITER == 0 && chunk == 0 && t < 32) {
        float a = 0.f;
        for (int j = 0; j < 98; j++) a += d_pspart[(b * 98 + j) * 32 + t];
        d_phisum[b * 32 + t] = a;
    }

    // stage phi (512 f4) and g (1024 f4)
    {
        const float4* phg = (const float4*)(d_phi + row0 * 32);
        const float4* gg  = (const float4*)(g + row0 * 64);
#pragma unroll
        for (int j = 0; j < 2; j++) {
            int e = t + j * 256;
            int r = e >> 3, d4 = (e & 7) * 4;
            *(float4*)(sph + r * 36 + d4) = phg[e];
        }
#pragma unroll
        for (int j = 0; j < 4; j++) {
            int e = t + j * 256;
            int r = e >> 4, c4 = (e & 15) * 4;
            *(float4*)(sg + r * 68 + c4) = gg[e];
        }
    }
    __syncthreads();

    int w = t >> 5, lane = t & 31;
    int gq = lane >> 2, tg = lane & 3;
    int db = (w & 1) * 16;          // d band
    int ct = (w >> 1) * 8;          // col tile base; tiles at ct and ct+32

    float4 c0 = make_float4(0.f, 0.f, 0.f, 0.f);
    float4 c1v = make_float4(0.f, 0.f, 0.f, 0.f);

#pragma unroll
    for (int kb = 0; kb < 64; kb += 8) {
        // A = phi^T: a_row = d, a_col = k(row). a0=A[gq][tg]=phi[kb+tg][db+gq]
        unsigned a0 = tf32(sph[(kb + tg) * 36 + db + gq]);
        unsigned a1 = tf32(sph[(kb + tg) * 36 + db + gq + 8]);
        unsigned a2 = tf32(sph[(kb + tg + 4) * 36 + db + gq]);
        unsigned a3 = tf32(sph[(kb + tg + 4) * 36 + db + gq + 8]);
        // B tile 0 (cols ct..ct+7): b0=B[tg][gq]=g[kb+tg][ct+gq]
        unsigned b0 = tf32(sg[(kb + tg) * 68 + ct + gq]);
        unsigned b1 = tf32(sg[(kb + tg + 4) * 68 + ct + gq]);
        mma_tf32(c0, a0, a1, a2, a3, b0, b1);
        // B tile 1 (cols ct+32..)
        unsigned b2 = tf32(sg[(kb + tg) * 68 + ct + 32 + gq]);
        unsigned b3 = tf32(sg[(kb + tg + 4) * 68 + ct + 32 + gq]);
        mma_tf32(c1v, a0, a1, a2, a3, b2, b3);
    }
    __syncthreads();   // all fragment reads done; overlay partial

    // C frag -> part[d][c]: c0/c1 at row db+gq, c2/c3 at row db+gq+8
    {
        int cA = ct + tg * 2;
        *(float2*)(part + (db + gq) * 68 + cA)     = make_float2(c0.x, c0.y);
        *(float2*)(part + (db + gq + 8) * 68 + cA) = make_float2(c0.z, c0.w);
        *(float2*)(part + (db + gq) * 68 + cA + 32)     = make_float2(c1v.x, c1v.y);
        *(float2*)(part + (db + gq + 8) * 68 + cA + 32) = make_float2(c1v.z, c1v.w);
    }
    __syncthreads();

    // emission (R8/R9-proven): 2x v4 REDG per thread, coalesced rows
    int dd = t >> 3, cc = (t & 7) * 8;
    const float* p0 = part + dd * 68 + cc;
    float4 e0 = *(const float4*)(p0);
    float4 e1 = *(const float4*)(p0 + 4);
    float* Mb = d_M[ITER] + b * 2048 + dd * 64 + cc;
    redg_v4(Mb,     e0.x, e0.y, e0.z, e0.w);
    redg_v4(Mb + 4, e1.x, e1.y, e1.z, e1.w);
}

// ===========================================================================
// K3/K5: two-phase apply via tf32 MMA.
//   phase1: raw = theta @ M (K=32); fg = (lam/N)*raw - (s/N)*g  (fp32 correction)
//   phase2: o = fg @ W (K=64); bias+BN+ReLU; out = x + 0.05*o
// 8 warps: warp w owns row band (w>>1)*16 and col half (w&1)*32 (4 n8 tiles).
template<int ITER>
__global__ void __launch_bounds__(256) k_apply(
        const float* __restrict__ x,
        const float* __restrict__ Wst, const float* __restrict__ bst,
        const float* __restrict__ gam, const float* __restrict__ bet,
        const float* __restrict__ mmean, const float* __restrict__ mvar,
        float* __restrict__ out_ext) {
    const float* gin = ITER ? d_g1 : x;
    float* out       = ITER ? out_ext : d_g1;

    __shared__ float sm[9184];
    float* sTh = sm;           // theta [row 64][d 32] pad 36   (2304)
    float* sM  = sm + 2304;    // M [k 32][c 64] pad 68          (2176)
    float* sW  = sm + 4480;    // W [k 64][c 64] pad 68          (4352)
    float* sFg = sm;           // overlay: fg [row 64][k 64] pad 68 (4352 <= 4480)
    float* sP  = sm + 8832;    // params: scl,bia,mean,betc  (4*64)
    float* ss  = sm + 9088;    // 64
    float* sps = sm + 9152;    // 32

    int t  = threadIdx.x;
    int r0 = blockIdx.x * 64;
    int b  = blockIdx.x / 49;

    // stage theta [row][d] pad 36
    {
        const float4* thg = (const float4*)(d_theta + r0 * 32);
#pragma unroll
        for (int j = 0; j < 2; j++) {
            int e = t + j * 256;
            int r = e >> 3, d4 = (e & 7) * 4;
            *(float4*)(sTh + r * 36 + d4) = thg[e];
        }
    }
    // stage M [k][c] pad 68
    const float* Mi = d_M[ITER] + b * 2048;
#pragma unroll
    for (int j = 0; j < 2; j++) {
        int e = t + j * 256;
        int k = e >> 4, c4 = (e & 15) * 4;
        *(float4*)(sM + k * 68 + c4) = ((const float4*)Mi)[e];
    }
    // stage W [k][c] pad 68
    const float* Wi = Wst + ITER * 4096;
#pragma unroll
    for (int j = 0; j < 4; j++) {
        int e = t + j * 256;
        int k = e >> 4, c4 = (e & 15) * 4;
        *(float4*)(sW + k * 68 + c4) = ((const float4*)Wi)[e];
    }
    // stage BN params per col
    if (t < 64) {
        int ic = ITER * 64 + t;
        sP[t]       = gam[ic] * rsqrtf(mvar[ic] + BNEPS);
        sP[64 + t]  = bst[ic];
        sP[128 + t] = mmean[ic];
        sP[192 + t] = bet[ic];
    }
    if (t < 32) sps[t] = d_phisum[b * 32 + t];
    __syncthreads();

    if (t < 64) {   // -(s/N) per row, s = LAM * theta . phisum
        float a = 0.f;
#pragma unroll
        for (int k = 0; k < 32; k++) a = fmaf(sTh[t * 36 + k], sps[k], a);
        ss[t] = a * (-LAMF * INVN);
    }
    __syncthreads();

    int w = t >> 5, lane = t & 31;
    int gq = lane >> 2, tg = lane & 3;
    int rb = (w >> 1) * 16;        // row band
    int ch = (w & 1) * 32;         // col half
    int row0l = rb + gq, row1l = rb + gq + 8;

    // ---- phase 1: raw = theta @ M (K=32), 4 n8 tiles ----
    float4 c[4];
#pragma unroll
    for (int i = 0; i < 4; i++) c[i] = make_float4(0.f, 0.f, 0.f, 0.f);

#pragma unroll
    for (int kb = 0; kb < 32; kb += 8) {
        unsigned a0 = tf32(sTh[row0l * 36 + kb + tg]);
        unsigned a1 = tf32(sTh[row1l * 36 + kb + tg]);
        unsigned a2 = tf32(sTh[row0l * 36 + kb + tg + 4]);
        unsigned a3 = tf32(sTh[row1l * 36 + kb + tg + 4]);
#pragma unroll
        for (int nt = 0; nt < 4; nt++) {
            int cb = ch + nt * 8;
            unsigned b0 = tf32(sM[(kb + tg) * 68 + cb + gq]);
            unsigned b1 = tf32(sM[(kb + tg + 4) * 68 + cb + gq]);
            mma_tf32(c[nt], a0, a1, a2, a3, b0, b1);
        }
    }
    // correction in fp32: fg = c1*raw + sneg*g
    {
        const float c1f = LAMF * INVN;
        float sn0 = ss[row0l], sn1 = ss[row1l];
#pragma unroll
        for (int nt = 0; nt < 4; nt++) {
            int cb2 = ch + nt * 8 + tg * 2;
            float2 g0 = *(const float2*)(gin + (r0 + row0l) * 64 + cb2);
            float2 g1 = *(const float2*)(gin + (r0 + row1l) * 64 + cb2);
            c[nt].x = fmaf(sn0, g0.x, c1f * c[nt].x);
            c[nt].y = fmaf(sn0, g0.y, c1f * c[nt].y);
            c[nt].z = fmaf(sn1, g1.x, c1f * c[nt].z);
            c[nt].w = fmaf(sn1, g1.y, c1f * c[nt].w);
        }
    }
    __syncthreads();   // all phase-1 fragment reads done; overlay sFg

    // write fg [row][k] pad 68
#pragma unroll
    for (int nt = 0; nt < 4; nt++) {
        int cb2 = ch + nt * 8 + tg * 2;
        *(float2*)(sFg + row0l * 68 + cb2) = make_float2(c[nt].x, c[nt].y);
        *(float2*)(sFg + row1l * 68 + cb2) = make_float2(c[nt].z, c[nt].w);
    }
    __syncthreads();

    // ---- phase 2: o = fg @ W (K=64) ----
    float4 o[4];
#pragma unroll
    for (int i = 0; i < 4; i++) o[i] = make_float4(0.f, 0.f, 0.f, 0.f);

#pragma unroll
    for (int kb = 0; kb < 64; kb += 8) {
        unsigned a0 = tf32(sFg[row0l * 68 + kb + tg]);
        unsigned a1 = tf32(sFg[row1l * 68 + kb + tg]);
        unsigned a2 = tf32(sFg[row0l * 68 + kb + tg + 4]);
        unsigned a3 = tf32(sFg[row1l * 68 + kb + tg + 4]);
#pragma unroll
        for (int nt = 0; nt < 4; nt++) {
            int cb = ch + nt * 8;
            unsigned b0 = tf32(sW[(kb + tg) * 68 + cb + gq]);
            unsigned b1 = tf32(sW[(kb + tg + 4) * 68 + cb + gq]);
            mma_tf32(o[nt], a0, a1, a2, a3, b0, b1);
        }
    }

    // epilogue: bias, BN, ReLU, residual (last == x always)
    int gr0 = r0 + row0l, gr1 = r0 + row1l;
#pragma unroll
    for (int nt = 0; nt < 4; nt++) {
        int cb2 = ch + nt * 8 + tg * 2;
        float scl0 = sP[cb2],       scl1 = sP[cb2 + 1];
        float bi0  = sP[64 + cb2],  bi1  = sP[64 + cb2 + 1];
        float mn0  = sP[128 + cb2], mn1  = sP[128 + cb2 + 1];
        float be0  = sP[192 + cb2], be1  = sP[192 + cb2 + 1];
        float2 x0 = *(const float2*)(x + gr0 * 64 + cb2);
        float2 x1 = *(const float2*)(x + gr1 * 64 + cb2);
        float o00 = fmaxf((o[nt].x + bi0 - mn0) * scl0 + be0, 0.f);
        float o01 = fmaxf((o[nt].y + bi1 - mn1) * scl1 + be1, 0.f);
        float o10 = fmaxf((o[nt].z + bi0 - mn0) * scl0 + be0, 0.f);
        float o11 = fmaxf((o[nt].w + bi1 - mn1) * scl1 + be1, 0.f);
        *(float2*)(out + gr0 * 64 + cb2) =
            make_float2(x0.x + HSTEP * o00, x0.y + HSTEP * o01);
        *(float2*)(out + gr1 * 64 + cb2) =
            make_float2(x1.x + HSTEP * o10, x1.y + HSTEP * o11);
    }
}

// ---------------------------------------------------------------------------
extern "C" void kernel_launch(void* const* d_in, const int* in_sizes, int n_in,
                              void* d_out, int out_size) {
    const float* x     = (const float*)d_in[0];
    const float* Wt    = (const float*)d_in[1];
    const float* bt    = (const float*)d_in[2];
    const float* Wp    = (const float*)d_in[3];
    const float* bp    = (const float*)d_in[4];
    const float* Wst   = (const float*)d_in[5];
    const float* bst   = (const float*)d_in[6];
    const float* gam   = (const float*)d_in[7];
    const float* bet   = (const float*)d_in[8];
    const float* mmean = (const float*)d_in[9];
    const float* mvar  = (const float*)d_in[10];
    float* out = (float*)d_out;

    k_theta_phi<<<BNROWS / 32, 256>>>(x, Wt, bt, Wp, bp);
    k_reduceM<0><<<Bb * 49, 256>>>(x);
    k_apply<0><<<BNROWS / 64, 256>>>(x, Wst, bst, gam, bet, mmean, mvar, out);
    k_reduceM<1><<<Bb * 49, 256>>>(x);
    k_apply<1><<<BNROWS / 64, 256>>>(x, Wst, bst, gam, bet, mmean, mvar, out);
}

// round 14
// speedup vs baseline: 1.9890x; 1.1302x over previous
#include <cuda_runtime.h>

#define Bb     8
#define Nn     3136
#define Cc     64
#define CI     32
#define BNROWS 25088          // Bb * Nn
#define LAMF   0.1f
#define HSTEP  0.05f
#define BNEPS  1e-3f
#define INVN   (1.0f / 3136.0f)

// ---- scratch (static device globals; no allocation) ----
__device__ float d_theta[BNROWS * CI];
__device__ float d_phi[BNROWS * CI];
__device__ float d_phisum[Bb * CI];      // published by k_apply<0> chunk-0 blocks
__device__ float d_pspart[392 * CI];     // per-front-block phi-sum partials
__device__ float d_M[2][Bb * 2048];      // REDG accum; scrubbed stream-ordered:
                                         //  d_M[1] zeroed by apply<0>, d_M[0] by reduceM1
__device__ float d_g1[BNROWS * Cc];

__device__ __forceinline__ void redg_v4(float* p, float a, float b, float c, float d) {
    asm volatile("red.global.add.v4.f32 [%0], {%1, %2, %3, %4};"
                 :: "l"(p), "f"(a), "f"(b), "f"(c), "f"(d) : "memory");
}
__device__ __forceinline__ unsigned tf32(float x) {
    unsigned r; asm("cvt.rna.tf32.f32 %0, %1;" : "=r"(r) : "f"(x)); return r;
}
__device__ __forceinline__ void mma_tf32(float4& d,
        unsigned a0, unsigned a1, unsigned a2, unsigned a3,
        unsigned b0, unsigned b1) {
    asm("mma.sync.aligned.m16n8k8.row.col.f32.tf32.tf32.f32 "
        "{%0,%1,%2,%3}, {%4,%5,%6,%7}, {%8,%9}, {%0,%1,%2,%3};"
        : "+f"(d.x), "+f"(d.y), "+f"(d.z), "+f"(d.w)
        : "r"(a0), "r"(a1), "r"(a2), "r"(a3), "r"(b0), "r"(b1));
}

// ===========================================================================
// K1 (front): 64 rows/block, grid 392.
//   theta/phi = x @ Wt/Wp + bias  (scalar GEMM, warp = 8 rows, lane = d)
//   + per-block phisum partial (plain store)
//   + fused M0 partial = phi^T x via tf32 MMA + v4 REDG (R13-proven pattern)
__global__ void __launch_bounds__(256) k_front(
        const float* __restrict__ x,
        const float* __restrict__ Wt, const float* __restrict__ bt,
        const float* __restrict__ Wp, const float* __restrict__ bp) {
    __shared__ float sm[11040];
    float* sx   = sm;            // x [row 64][c 64] pad 68   (4352)
    float* sWt  = sm + 4352;     // Wt^T [d 32][k 64] pad 68  (2176)
    float* sWp  = sm + 6528;     // Wp^T [d 32][k 64] pad 68  (2176)
    float* sph  = sm + 8704;     // phi [row 64][d 32] pad 36 (2304)
    float* sp   = sm + 11008;    // 32
    float* part = sm + 4352;     // overlay: M0 partial [d 32][c 64] pad 68 (2176)

    int t  = threadIdx.x;
    int gb = blockIdx.x;
    int b  = gb / 49;
    int r0 = gb * 64;

    // stage x [row][c] pad 68
    {
        const float4* xg = (const float4*)(x + r0 * 64);
#pragma unroll
        for (int j = 0; j < 4; j++) {
            int e = t + j * 256;
            int r = e >> 4, c4 = (e & 15) * 4;
            *(float4*)(sx + r * 68 + c4) = xg[e];
        }
    }
    // stage weights transposed [d][k] pad 68
    for (int e = t; e < 2048; e += 256) {
        int k = e >> 5, d = e & 31;
        sWt[d * 68 + k] = Wt[e];
        sWp[d * 68 + k] = Wp[e];
    }
    if (t < 32) sp[t] = 0.f;
    __syncthreads();

    // GEMM: warp w -> rows w*8..w*8+7, lane = d
    int w = t >> 5, d = t & 31;
    float th[8], ph[8];
    float bt_d = bt[d], bp_d = bp[d];
#pragma unroll
    for (int j = 0; j < 8; j++) { th[j] = bt_d; ph[j] = bp_d; }

    const float* xr = sx + w * 8 * 68;
    const float* wt = sWt + d * 68;
    const float* wp = sWp + d * 68;
#pragma unroll 8
    for (int k = 0; k < 64; k += 4) {
        float4 a = *(const float4*)(wt + k);
        float4 b2 = *(const float4*)(wp + k);
#pragma unroll
        for (int j = 0; j < 8; j++) {
            float4 xv = *(const float4*)(xr + j * 68 + k);
            th[j] = fmaf(xv.x, a.x, th[j]);  th[j] = fmaf(xv.y, a.y, th[j]);
            th[j] = fmaf(xv.z, a.z, th[j]);  th[j] = fmaf(xv.w, a.w, th[j]);
            ph[j] = fmaf(xv.x, b2.x, ph[j]); ph[j] = fmaf(xv.y, b2.y, ph[j]);
            ph[j] = fmaf(xv.z, b2.z, ph[j]); ph[j] = fmaf(xv.w, b2.w, ph[j]);
        }
    }
    int r = r0 + w * 8;
    float phs = 0.f;
#pragma unroll
    for (int j = 0; j < 8; j++) {
        d_theta[(r + j) * 32 + d] = th[j];
        d_phi[(r + j) * 32 + d]   = ph[j];
        sph[(w * 8 + j) * 36 + d] = ph[j];
        phs += ph[j];
    }
    atomicAdd(&sp[d], phs);
    __syncthreads();
    if (t < 32) d_pspart[gb * 32 + t] = sp[t];

    // ---- fused M0 partial via tf32 MMA (A = phi^T, B = x tile) ----
    int lane = t & 31;
    int gq = lane >> 2, tg = lane & 3;
    int db = (w & 1) * 16;          // d band
    int ct = (w >> 1) * 8;          // col tiles at ct and ct+32

    float4 c0 = make_float4(0.f, 0.f, 0.f, 0.f);
    float4 c1v = make_float4(0.f, 0.f, 0.f, 0.f);
#pragma unroll
    for (int kb = 0; kb < 64; kb += 8) {
        unsigned a0 = tf32(sph[(kb + tg) * 36 + db + gq]);
        unsigned a1 = tf32(sph[(kb + tg) * 36 + db + gq + 8]);
        unsigned a2 = tf32(sph[(kb + tg + 4) * 36 + db + gq]);
        unsigned a3 = tf32(sph[(kb + tg + 4) * 36 + db + gq + 8]);
        unsigned b0 = tf32(sx[(kb + tg) * 68 + ct + gq]);
        unsigned b1 = tf32(sx[(kb + tg + 4) * 68 + ct + gq]);
        mma_tf32(c0, a0, a1, a2, a3, b0, b1);
        unsigned b2 = tf32(sx[(kb + tg) * 68 + ct + 32 + gq]);
        unsigned b3 = tf32(sx[(kb + tg + 4) * 68 + ct + 32 + gq]);
        mma_tf32(c1v, a0, a1, a2, a3, b2, b3);
    }
    __syncthreads();   // sWt/sWp (GEMM) reads done; overlay partial

    {
        int cA = ct + tg * 2;
        *(float2*)(part + (db + gq) * 68 + cA)          = make_float2(c0.x, c0.y);
        *(float2*)(part + (db + gq + 8) * 68 + cA)      = make_float2(c0.z, c0.w);
        *(float2*)(part + (db + gq) * 68 + cA + 32)     = make_float2(c1v.x, c1v.y);
        *(float2*)(part + (db + gq + 8) * 68 + cA + 32) = make_float2(c1v.z, c1v.w);
    }
    __syncthreads();

    int dd = t >> 3, cc = (t & 7) * 8;
    const float* p0 = part + dd * 68 + cc;
    float4 e0 = *(const float4*)(p0);
    float4 e1 = *(const float4*)(p0 + 4);
    float* Mb = d_M[0] + b * 2048 + dd * 64 + cc;
    redg_v4(Mb,     e0.x, e0.y, e0.z, e0.w);
    redg_v4(Mb + 4, e1.x, e1.y, e1.z, e1.w);
}

// ===========================================================================
// K3 (reduceM1): M[1][b] += phi[b]^T @ g1[b] via tf32 MMA (R13-proven).
// Blocks 0-15 also zero d_M[0] (consumed by apply<0> one launch earlier;
// refilled only by next replay's k_front — stream-ordered, race-free).
__global__ void __launch_bounds__(256) k_reduceM1() {
    __shared__ float sm[6656];
    float* sph  = sm;          // phi [row 64][d 32] pad 36  (2304)
    float* sg   = sm + 2304;   // g1  [row 64][c 64] pad 68  (4352)
    float* part = sm;          // overlay: [d 32][c 64] pad 68 (2176)

    int t     = threadIdx.x;
    int b     = blockIdx.x / 49;
    int chunk = blockIdx.x % 49;
    int row0  = b * Nn + chunk * 64;

    if (blockIdx.x < 16)   // scrub d_M[0] for next replay
        ((float4*)d_M[0])[blockIdx.x * 256 + t] = make_float4(0.f, 0.f, 0.f, 0.f);

    {
        const float4* phg = (const float4*)(d_phi + row0 * 32);
        const float4* gg  = (const float4*)(d_g1 + row0 * 64);
#pragma unroll
        for (int j = 0; j < 2; j++) {
            int e = t + j * 256;
            int r = e >> 3, d4 = (e & 7) * 4;
            *(float4*)(sph + r * 36 + d4) = phg[e];
        }
#pragma unroll
        for (int j = 0; j < 4; j++) {
            int e = t + j * 256;
            int r = e >> 4, c4 = (e & 15) * 4;
            *(float4*)(sg + r * 68 + c4) = gg[e];
        }
    }
    __syncthreads();

    int w = t >> 5, lane = t & 31;
    int gq = lane >> 2, tg = lane & 3;
    int db = (w & 1) * 16;
    int ct = (w >> 1) * 8;

    float4 c0 = make_float4(0.f, 0.f, 0.f, 0.f);
    float4 c1v = make_float4(0.f, 0.f, 0.f, 0.f);
#pragma unroll
    for (int kb = 0; kb < 64; kb += 8) {
        unsigned a0 = tf32(sph[(kb + tg) * 36 + db + gq]);
        unsigned a1 = tf32(sph[(kb + tg) * 36 + db + gq + 8]);
        unsigned a2 = tf32(sph[(kb + tg + 4) * 36 + db + gq]);
        unsigned a3 = tf32(sph[(kb + tg + 4) * 36 + db + gq + 8]);
        unsigned b0 = tf32(sg[(kb + tg) * 68 + ct + gq]);
        unsigned b1 = tf32(sg[(kb + tg + 4) * 68 + ct + gq]);
        mma_tf32(c0, a0, a1, a2, a3, b0, b1);
        unsigned b2 = tf32(sg[(kb + tg) * 68 + ct + 32 + gq]);
        unsigned b3 = tf32(sg[(kb + tg + 4) * 68 + ct + 32 + gq]);
        mma_tf32(c1v, a0, a1, a2, a3, b2, b3);
    }
    __syncthreads();

    {
        int cA = ct + tg * 2;
        *(float2*)(part + (db + gq) * 68 + cA)          = make_float2(c0.x, c0.y);
        *(float2*)(part + (db + gq + 8) * 68 + cA)      = make_float2(c0.z, c0.w);
        *(float2*)(part + (db + gq) * 68 + cA + 32)     = make_float2(c1v.x, c1v.y);
        *(float2*)(part + (db + gq + 8) * 68 + cA + 32) = make_float2(c1v.z, c1v.w);
    }
    __syncthreads();

    int dd = t >> 3, cc = (t & 7) * 8;
    const float* p0 = part + dd * 68 + cc;
    float4 e0 = *(const float4*)(p0);
    float4 e1 = *(const float4*)(p0 + 4);
    float* Mb = d_M[1] + b * 2048 + dd * 64 + cc;
    redg_v4(Mb,     e0.x, e0.y, e0.z, e0.w);
    redg_v4(Mb + 4, e1.x, e1.y, e1.z, e1.w);
}

// ===========================================================================
// K2/K4 (apply): two-phase tf32-MMA apply (R13-proven core).
// ITER==0: phisum reduced in-block from d_pspart (chunk-0 publishes d_phisum),
//          blocks 0-15 zero d_M[1] (REDG'd only by the LATER reduceM1 launch).
// ITER==1: phisum read from d_phisum.
template<int ITER>
__global__ void __launch_bounds__(256) k_apply(
        const float* __restrict__ x,
        const float* __restrict__ Wst, const float* __restrict__ bst,
        const float* __restrict__ gam, const float* __restrict__ bet,
        const float* __restrict__ mmean, const float* __restrict__ mvar,
        float* __restrict__ out_ext) {
    const float* gin = ITER ? d_g1 : x;
    float* out       = ITER ? out_ext : d_g1;

    __shared__ float sm[9440];
    float* sTh  = sm;           // theta [row 64][d 32] pad 36   (2304)
    float* sM   = sm + 2304;    // M [k 32][c 64] pad 68          (2176)
    float* sW   = sm + 4480;    // W [k 64][c 64] pad 68          (4352)
    float* sFg  = sm;           // overlay: fg [row 64][k 64] pad 68 (4352)
    float* sP   = sm + 8832;    // params: scl,bia,mean,betc (256)
    float* ss   = sm + 9088;    // 64
    float* sps  = sm + 9152;    // 32
    float* sred = sm + 9184;    // 256 (ITER==0 phisum reduce)

    int t  = threadIdx.x;
    int r0 = blockIdx.x * 64;
    int b  = blockIdx.x / 49;
    int chunk = blockIdx.x % 49;

    if (ITER == 0 && blockIdx.x < 16)   // scrub d_M[1] before reduceM1 REDGs it
        ((float4*)d_M[1])[blockIdx.x * 256 + t] = make_float4(0.f, 0.f, 0.f, 0.f);

    // stage theta [row][d] pad 36
    {
        const float4* thg = (const float4*)(d_theta + r0 * 32);
#pragma unroll
        for (int j = 0; j < 2; j++) {
            int e = t + j * 256;
            int r = e >> 3, d4 = (e & 7) * 4;
            *(float4*)(sTh + r * 36 + d4) = thg[e];
        }
    }
    // stage M [k][c] pad 68
    const float* Mi = d_M[ITER] + b * 2048;
#pragma unroll
    for (int j = 0; j < 2; j++) {
        int e = t + j * 256;
        int k = e >> 4, c4 = (e & 15) * 4;
        *(float4*)(sM + k * 68 + c4) = ((const float4*)Mi)[e];
    }
    // stage W [k][c] pad 68
    const float* Wi = Wst + ITER * 4096;
#pragma unroll
    for (int j = 0; j < 4; j++) {
        int e = t + j * 256;
        int k = e >> 4, c4 = (e & 15) * 4;
        *(float4*)(sW + k * 68 + c4) = ((const float4*)Wi)[e];
    }
    // BN params
    if (t < 64) {
        int ic = ITER * 64 + t;
        sP[t]       = gam[ic] * rsqrtf(mvar[ic] + BNEPS);
        sP[64 + t]  = bst[ic];
        sP[128 + t] = mmean[ic];
        sP[192 + t] = bet[ic];
    }
    // phisum
    if (ITER == 0) {
        int lane = t & 31, grp = t >> 5;
        float a = 0.f;
        for (int j = grp; j < 49; j += 8)
            a += d_pspart[(b * 49 + j) * 32 + lane];
        sred[grp * 32 + lane] = a;
    } else {
        if (t < 32) sps[t] = d_phisum[b * 32 + t];
    }
    __syncthreads();
    if (ITER == 0) {
        if (t < 32) {
            float a = 0.f;
#pragma unroll
            for (int g2 = 0; g2 < 8; g2++) a += sred[g2 * 32 + t];
            sps[t] = a;
            if (chunk == 0) d_phisum[b * 32 + t] = a;   // publish for apply<1>
        }
        __syncthreads();
    }

    if (t < 64) {   // -(s/N) per row
        float a = 0.f;
#pragma unroll
        for (int k = 0; k < 32; k++) a = fmaf(sTh[t * 36 + k], sps[k], a);
        ss[t] = a * (-LAMF * INVN);
    }
    __syncthreads();

    int w = t >> 5, lane = t & 31;
    int gq = lane >> 2, tg = lane & 3;
    int rb = (w >> 1) * 16;
    int ch = (w & 1) * 32;
    int row0l = rb + gq, row1l = rb + gq + 8;

    // ---- phase 1: raw = theta @ M (K=32) ----
    float4 c[4];
#pragma unroll
    for (int i = 0; i < 4; i++) c[i] = make_float4(0.f, 0.f, 0.f, 0.f);
#pragma unroll
    for (int kb = 0; kb < 32; kb += 8) {
        unsigned a0 = tf32(sTh[row0l * 36 + kb + tg]);
        unsigned a1 = tf32(sTh[row1l * 36 + kb + tg]);
        unsigned a2 = tf32(sTh[row0l * 36 + kb + tg + 4]);
        unsigned a3 = tf32(sTh[row1l * 36 + kb + tg + 4]);
#pragma unroll
        for (int nt = 0; nt < 4; nt++) {
            int cb = ch + nt * 8;
            unsigned b0 = tf32(sM[(kb + tg) * 68 + cb + gq]);
            unsigned b1 = tf32(sM[(kb + tg + 4) * 68 + cb + gq]);
            mma_tf32(c[nt], a0, a1, a2, a3, b0, b1);
        }
    }
    {
        const float c1f = LAMF * INVN;
        float sn0 = ss[row0l], sn1 = ss[row1l];
#pragma unroll
        for (int nt = 0; nt < 4; nt++) {
            int cb2 = ch + nt * 8 + tg * 2;
            float2 g0 = *(const float2*)(gin + (r0 + row0l) * 64 + cb2);
            float2 g1 = *(const float2*)(gin + (r0 + row1l) * 64 + cb2);
            c[nt].x = fmaf(sn0, g0.x, c1f * c[nt].x);
            c[nt].y = fmaf(sn0, g0.y, c1f * c[nt].y);
            c[nt].z = fmaf(sn1, g1.x, c1f * c[nt].z);
            c[nt].w = fmaf(sn1, g1.y, c1f * c[nt].w);
        }
    }
    __syncthreads();

    // fg [row][k] pad 68
#pragma unroll
    for (int nt = 0; nt < 4; nt++) {
        int cb2 = ch + nt * 8 + tg * 2;
        *(float2*)(sFg + row0l * 68 + cb2) = make_float2(c[nt].x, c[nt].y);
        *(float2*)(sFg + row1l * 68 + cb2) = make_float2(c[nt].z, c[nt].w);
    }
    __syncthreads();

    // ---- phase 2: o = fg @ W (K=64) ----
    float4 o[4];
#pragma unroll
    for (int i = 0; i < 4; i++) o[i] = make_float4(0.f, 0.f, 0.f, 0.f);
#pragma unroll
    for (int kb = 0; kb < 64; kb += 8) {
        unsigned a0 = tf32(sFg[row0l * 68 + kb + tg]);
        unsigned a1 = tf32(sFg[row1l * 68 + kb + tg]);
        unsigned a2 = tf32(sFg[row0l * 68 + kb + tg + 4]);
        unsigned a3 = tf32(sFg[row1l * 68 + kb + tg + 4]);
#pragma unroll
        for (int nt = 0; nt < 4; nt++) {
            int cb = ch + nt * 8;
            unsigned b0 = tf32(sW[(kb + tg) * 68 + cb + gq]);
            unsigned b1 = tf32(sW[(kb + tg + 4) * 68 + cb + gq]);
            mma_tf32(o[nt], a0, a1, a2, a3, b0, b1);
        }
    }

    // epilogue
    int gr0 = r0 + row0l, gr1 = r0 + row1l;
#pragma unroll
    for (int nt = 0; nt < 4; nt++) {
        int cb2 = ch + nt * 8 + tg * 2;
        float scl0 = sP[cb2],       scl1 = sP[cb2 + 1];
        float bi0  = sP[64 + cb2],  bi1  = sP[64 + cb2 + 1];
        float mn0  = sP[128 + cb2], mn1  = sP[128 + cb2 + 1];
        float be0  = sP[192 + cb2], be1  = sP[192 + cb2 + 1];
        float2 x0 = *(const float2*)(x + gr0 * 64 + cb2);
        float2 x1 = *(const float2*)(x + gr1 * 64 + cb2);
        float o00 = fmaxf((o[nt].x + bi0 - mn0) * scl0 + be0, 0.f);
        float o01 = fmaxf((o[nt].y + bi1 - mn1) * scl1 + be1, 0.f);
        float o10 = fmaxf((o[nt].z + bi0 - mn0) * scl0 + be0, 0.f);
        float o11 = fmaxf((o[nt].w + bi1 - mn1) * scl1 + be1, 0.f);
        *(float2*)(out + gr0 * 64 + cb2) =
            make_float2(x0.x + HSTEP * o00, x0.y + HSTEP * o01);
        *(float2*)(out + gr1 * 64 + cb2) =
            make_float2(x1.x + HSTEP * o10, x1.y + HSTEP * o11);
    }
}

// ---------------------------------------------------------------------------
extern "C" void kernel_launch(void* const* d_in, const int* in_sizes, int n_in,
                              void* d_out, int out_size) {
    const float* x     = (const float*)d_in[0];
    const float* Wt    = (const float*)d_in[1];
    const float* bt    = (const float*)d_in[2];
    const float* Wp    = (const float*)d_in[3];
    const float* bp    = (const float*)d_in[4];
    const float* Wst   = (const float*)d_in[5];
    const float* bst   = (const float*)d_in[6];
    const float* gam   = (const float*)d_in[7];
    const float* bet   = (const float*)d_in[8];
    const float* mmean = (const float*)d_in[9];
    const float* mvar  = (const float*)d_in[10];
    float* out = (float*)d_out;

    k_front<<<Bb * 49, 256>>>(x, Wt, bt, Wp, bp);
    k_apply<0><<<BNROWS / 64, 256>>>(x, Wst, bst, gam, bet, mmean, mvar, out);
    k_reduceM1<<<Bb * 49, 256>>>();
    k_apply<1><<<BNROWS / 64, 256>>>(x, Wst, bst, gam, bet, mmean, mvar, out);
}